// round 14
// baseline (speedup 1.0000x reference)
#include <cuda_runtime.h>
#include <math.h>

// Quaternion LSTM: T=128, B=64, F=512, H=1024.
// Round 14: best-of composition:
//   - gemm_in/out: R12 double-buffered gemm_body (proven win)
//   - recurrence: R7 simple loop (proven best) + chunk-order rotation so
//     co-resident CTAs' load phases interleave (covers L2 latency)
//   - R7 atomic grid barrier, concentrated update (CTAs 0-63)

#define T_ 128
#define B_ 64
#define Fdim 512
#define H_ 1024
#define N4 (4 * H_)          // 4096
#define FO (Fdim + 1)        // 513
#define SPLITK 8
#define KCHUNK (H_ / SPLITK) // 128
#define NCTA 256

// ---- scratch (static device globals: allocation-free) ----
__device__ float g_Wcat[(size_t)Fdim * N4];            //  8 MB
__device__ float g_bias4[N4];
__device__ float g_Ucat[(size_t)H_ * N4];              // 16 MB
__device__ float g_G[(size_t)T_ * B_ * N4];            // 128 MB (pre-gates)
__device__ float g_preK[(size_t)SPLITK * B_ * N4];     //  8 MB
__device__ float g_h[B_ * H_];
__device__ float g_c[B_ * H_];
__device__ float g_Hbuf[(size_t)T_ * B_ * H_];         // 32 MB
__device__ unsigned g_cnt;
__device__ volatile unsigned g_gen;

__device__ const float c_sgn[16] = {
    1.f, -1.f, -1.f, -1.f,
    1.f,  1.f, -1.f,  1.f,
    1.f,  1.f,  1.f, -1.f,
    1.f, -1.f,  1.f,  1.f
};

// ---------------- builds ----------------
__global__ void build_W(const float* __restrict__ wf, const float* __restrict__ wi,
                        const float* __restrict__ wo, const float* __restrict__ wc) {
    int idx = blockIdx.x * blockDim.x + threadIdx.x;
    if (idx >= Fdim * N4) return;
    int row  = idx / N4;
    int col  = idx % N4;
    int gate = col / H_;
    int cj   = col % H_;
    int rb = row / (Fdim / 4), a = row % (Fdim / 4);
    int cb = cj / (H_ / 4),    b = cj % (H_ / 4);
    const float* w = (gate == 0) ? wf : (gate == 1) ? wi : (gate == 2) ? wo : wc;
    g_Wcat[idx] = c_sgn[cb * 4 + rb] *
                  w[((size_t)(rb ^ cb) * (Fdim / 4) + a) * (H_ / 4) + b];
}

// build_U + state/bias/barrier init (keeps recurrence at launch slot 4)
__global__ void build_U_init(const float* __restrict__ uf, const float* __restrict__ ui,
                             const float* __restrict__ uo, const float* __restrict__ uc,
                             const float* __restrict__ bf, const float* __restrict__ bi,
                             const float* __restrict__ bo, const float* __restrict__ bc) {
    int idx = blockIdx.x * blockDim.x + threadIdx.x;
    if (idx < B_ * H_) { g_h[idx] = 0.f; g_c[idx] = 0.f; }
    if (idx == 0) { g_cnt = 0; g_gen = 0; }
    if (idx < N4) {
        int gate = idx / H_, j = idx % H_;
        const float* b = (gate == 0) ? bf : (gate == 1) ? bi : (gate == 2) ? bo : bc;
        g_bias4[idx] = b[j];
    }
    if (idx >= H_ * N4) return;
    int row  = idx / N4;
    int col  = idx % N4;
    int gate = col / H_;
    int cj   = col % H_;
    int rb = row / (H_ / 4), a = row % (H_ / 4);
    int cb = cj / (H_ / 4),  b = cj % (H_ / 4);
    const float* w = (gate == 0) ? uf : (gate == 1) ? ui : (gate == 2) ? uo : uc;
    g_Ucat[idx] = c_sgn[cb * 4 + rb] *
                  w[((size_t)(rb ^ cb) * (H_ / 4) + a) * (H_ / 4) + b];
}

// ---------------- generic fp32 GEMM, double-buffered (R12-proven) ----------------
__device__ __forceinline__ void gemm_body(const float* __restrict__ A,
                                          const float* __restrict__ Bm,
                                          const float* __restrict__ bias,
                                          float* __restrict__ C,
                                          int M, int N, int K) {
    const int BM = 128, BN = 128, BK = 16;
    __shared__ __align__(16) float As[2][BK][BM];
    __shared__ __align__(16) float Bs[2][BK][BN];
    int tid = threadIdx.x;
    int tx = tid % 16, ty = tid / 16;
    int rowBase = blockIdx.y * BM;
    int colBase = blockIdx.x * BN;
    bool fullN = ((N & 3) == 0) && (colBase + BN <= N);
    float acc[8][8];
    #pragma unroll
    for (int i = 0; i < 8; i++)
        #pragma unroll
        for (int j = 0; j < 8; j++) acc[i][j] = 0.f;

    {   // preload chunk 0
        #pragma unroll
        for (int i = 0; i < 2; i++) {
            int lin = tid + i * 256;
            int r = lin >> 2, c4 = (lin & 3) * 4;
            float4 v = *reinterpret_cast<const float4*>(
                &A[(size_t)(rowBase + r) * K + c4]);
            As[0][c4 + 0][r] = v.x;
            As[0][c4 + 1][r] = v.y;
            As[0][c4 + 2][r] = v.z;
            As[0][c4 + 3][r] = v.w;
        }
        if (fullN) {
            #pragma unroll
            for (int i = 0; i < 2; i++) {
                int lin = tid + i * 256;
                int kk = lin >> 5, c4 = (lin & 31) * 4;
                float4 v = *reinterpret_cast<const float4*>(
                    &Bm[(size_t)kk * N + colBase + c4]);
                *reinterpret_cast<float4*>(&Bs[0][kk][c4]) = v;
            }
        } else {
            #pragma unroll
            for (int i = 0; i < 8; i++) {
                int lin = tid + i * 256;
                int kk = lin >> 7, n = lin & 127;
                int gn = colBase + n;
                Bs[0][kk][n] = (gn < N) ? Bm[(size_t)kk * N + gn] : 0.f;
            }
        }
    }
    __syncthreads();

    int buf = 0;
    for (int k0 = 0; k0 < K; k0 += BK) {
        bool more = (k0 + BK) < K;
        float4 pa[2];
        float4 pbv[2];
        float pbs[8];
        if (more) {
            int kn = k0 + BK;
            #pragma unroll
            for (int i = 0; i < 2; i++) {
                int lin = tid + i * 256;
                int r = lin >> 2, c4 = (lin & 3) * 4;
                pa[i] = *reinterpret_cast<const float4*>(
                    &A[(size_t)(rowBase + r) * K + kn + c4]);
            }
            if (fullN) {
                #pragma unroll
                for (int i = 0; i < 2; i++) {
                    int lin = tid + i * 256;
                    int kk = lin >> 5, c4 = (lin & 31) * 4;
                    pbv[i] = *reinterpret_cast<const float4*>(
                        &Bm[(size_t)(kn + kk) * N + colBase + c4]);
                }
            } else {
                #pragma unroll
                for (int i = 0; i < 8; i++) {
                    int lin = tid + i * 256;
                    int kk = lin >> 7, n = lin & 127;
                    int gn = colBase + n;
                    pbs[i] = (gn < N) ? Bm[(size_t)(kn + kk) * N + gn] : 0.f;
                }
            }
        }
        #pragma unroll
        for (int kk = 0; kk < BK; kk++) {
            float a[8], b[8];
            float4 a0 = *reinterpret_cast<const float4*>(&As[buf][kk][ty * 8]);
            float4 a1 = *reinterpret_cast<const float4*>(&As[buf][kk][ty * 8 + 4]);
            float4 b0 = *reinterpret_cast<const float4*>(&Bs[buf][kk][tx * 8]);
            float4 b1 = *reinterpret_cast<const float4*>(&Bs[buf][kk][tx * 8 + 4]);
            a[0]=a0.x; a[1]=a0.y; a[2]=a0.z; a[3]=a0.w;
            a[4]=a1.x; a[5]=a1.y; a[6]=a1.z; a[7]=a1.w;
            b[0]=b0.x; b[1]=b0.y; b[2]=b0.z; b[3]=b0.w;
            b[4]=b1.x; b[5]=b1.y; b[6]=b1.z; b[7]=b1.w;
            #pragma unroll
            for (int i = 0; i < 8; i++)
                #pragma unroll
                for (int j = 0; j < 8; j++)
                    acc[i][j] += a[i] * b[j];
        }
        if (more) {
            int nb = buf ^ 1;
            #pragma unroll
            for (int i = 0; i < 2; i++) {
                int lin = tid + i * 256;
                int r = lin >> 2, c4 = (lin & 3) * 4;
                As[nb][c4 + 0][r] = pa[i].x;
                As[nb][c4 + 1][r] = pa[i].y;
                As[nb][c4 + 2][r] = pa[i].z;
                As[nb][c4 + 3][r] = pa[i].w;
            }
            if (fullN) {
                #pragma unroll
                for (int i = 0; i < 2; i++) {
                    int lin = tid + i * 256;
                    int kk = lin >> 5, c4 = (lin & 31) * 4;
                    *reinterpret_cast<float4*>(&Bs[nb][kk][c4]) = pbv[i];
                }
            } else {
                #pragma unroll
                for (int i = 0; i < 8; i++) {
                    int lin = tid + i * 256;
                    int kk = lin >> 7, n = lin & 127;
                    Bs[nb][kk][n] = pbs[i];
                }
            }
        }
        __syncthreads();
        buf ^= 1;
    }
    #pragma unroll
    for (int i = 0; i < 8; i++) {
        int gm = rowBase + ty * 8 + i;
        if (gm >= M) continue;
        #pragma unroll
        for (int j = 0; j < 8; j++) {
            int gn = colBase + tx * 8 + j;
            if (gn >= N) continue;
            float v = acc[i][j];
            if (bias) v += bias[gn];
            C[(size_t)gm * N + gn] = v;
        }
    }
}

__global__ __launch_bounds__(256) void gemm_in(const float* __restrict__ x) {
    gemm_body(x, g_Wcat, g_bias4, g_G, T_ * B_, N4, Fdim);
}

__global__ __launch_bounds__(256) void gemm_out(const float* __restrict__ fw,
                                                const float* __restrict__ fb,
                                                float* __restrict__ out) {
    gemm_body(g_Hbuf, fw, fb, out, T_ * B_, FO, H_);
}

// ---------------- grid barrier (R7-proven atomic version) ----------------
__device__ __forceinline__ void grid_barrier() {
    __syncthreads();
    __threadfence();
    if (threadIdx.x == 0) {
        unsigned gen = g_gen;
        unsigned prev = atomicAdd(&g_cnt, 1u);
        if (prev == NCTA - 1) {
            g_cnt = 0;
            __threadfence();
            g_gen = gen + 1;
        } else {
            while (g_gen == gen) { }
        }
    }
    __syncthreads();
    __threadfence();
}

// ---------------- persistent recurrence (R7 loop + chunk rotation) ------------
__global__ __launch_bounds__(256, 2) void recurrence() {
    __shared__ float As[16][68];
    __shared__ float Bs[16][132];
    int tid = threadIdx.x;
    int tx = tid & 15, ty = tid >> 4;
    int nTile = blockIdx.x & 31;
    int s = blockIdx.x >> 5;
    int colBase = nTile * 128;
    int kbase = s * KCHUNK;
    int gtid = blockIdx.x * 256 + tid;
    float* preOut = g_preK + (size_t)s * B_ * N4;
    int ar = tid >> 2, ac4 = (tid & 3) * 4;
    int rot = blockIdx.x & 7;   // co-resident CTAs (bid, bid+148) differ by 4

    for (int t = 0; t < T_; t++) {
        // ======== phase 1: pre = h @ Ucat (64 x 128 tile, K chunk s)
        float acc[4][8];
        #pragma unroll
        for (int i = 0; i < 4; i++)
            #pragma unroll
            for (int j = 0; j < 8; j++) acc[i][j] = 0.f;

        #pragma unroll 1
        for (int ci = 0; ci < 8; ci++) {
            int k0 = (((rot + ci) & 7) << 4);   // rotated chunk order
            // issue all 3 LDGs first (MLP 3), then stores
            float4 vb0, vb1, va;
            {
                int lin0 = tid;
                int kk0 = lin0 >> 5, c40 = (lin0 & 31) * 4;
                vb0 = *reinterpret_cast<const float4*>(
                    &g_Ucat[(size_t)(kbase + k0 + kk0) * N4 + colBase + c40]);
                int lin1 = tid + 256;
                int kk1 = lin1 >> 5, c41 = (lin1 & 31) * 4;
                vb1 = *reinterpret_cast<const float4*>(
                    &g_Ucat[(size_t)(kbase + k0 + kk1) * N4 + colBase + c41]);
                va = *reinterpret_cast<const float4*>(
                    &g_h[(size_t)ar * H_ + kbase + k0 + ac4]);
                *reinterpret_cast<float4*>(&Bs[kk0][c40]) = vb0;
                *reinterpret_cast<float4*>(&Bs[kk1][c41]) = vb1;
                As[ac4 + 0][ar] = va.x;
                As[ac4 + 1][ar] = va.y;
                As[ac4 + 2][ar] = va.z;
                As[ac4 + 3][ar] = va.w;
            }
            __syncthreads();
            #pragma unroll
            for (int kk = 0; kk < 16; kk++) {
                float4 av = *reinterpret_cast<const float4*>(&As[kk][ty * 4]);
                float4 b0 = *reinterpret_cast<const float4*>(&Bs[kk][tx * 8]);
                float4 b1 = *reinterpret_cast<const float4*>(&Bs[kk][tx * 8 + 4]);
                float a[4] = {av.x, av.y, av.z, av.w};
                float b[8] = {b0.x, b0.y, b0.z, b0.w, b1.x, b1.y, b1.z, b1.w};
                #pragma unroll
                for (int i = 0; i < 4; i++)
                    #pragma unroll
                    for (int j = 0; j < 8; j++)
                        acc[i][j] += a[i] * b[j];
            }
            __syncthreads();
        }
        #pragma unroll
        for (int i = 0; i < 4; i++) {
            int r = ty * 4 + i;
            float4 v0 = {acc[i][0], acc[i][1], acc[i][2], acc[i][3]};
            float4 v1 = {acc[i][4], acc[i][5], acc[i][6], acc[i][7]};
            *reinterpret_cast<float4*>(&preOut[(size_t)r * N4 + colBase + tx * 8])     = v0;
            *reinterpret_cast<float4*>(&preOut[(size_t)r * N4 + colBase + tx * 8 + 4]) = v1;
        }

        grid_barrier();

        // ======== phase 2: gates + state update (concentrated: CTAs 0-63)
        if (gtid < B_ * H_ / 4) {
            int b = gtid / (H_ / 4);
            int j = (gtid % (H_ / 4)) * 4;
            const float* Gt = g_G + (size_t)((size_t)t * B_ + b) * N4;
            float4 pf = *reinterpret_cast<const float4*>(&Gt[0 * H_ + j]);
            float4 pi = *reinterpret_cast<const float4*>(&Gt[1 * H_ + j]);
            float4 po = *reinterpret_cast<const float4*>(&Gt[2 * H_ + j]);
            float4 pa = *reinterpret_cast<const float4*>(&Gt[3 * H_ + j]);
            #pragma unroll
            for (int sp = 0; sp < SPLITK; sp++) {
                const float* pk = g_preK + (size_t)sp * B_ * N4 + (size_t)b * N4;
                float4 vf = *reinterpret_cast<const float4*>(&pk[0 * H_ + j]);
                float4 vi = *reinterpret_cast<const float4*>(&pk[1 * H_ + j]);
                float4 vo = *reinterpret_cast<const float4*>(&pk[2 * H_ + j]);
                float4 va = *reinterpret_cast<const float4*>(&pk[3 * H_ + j]);
                pf.x += vf.x; pf.y += vf.y; pf.z += vf.z; pf.w += vf.w;
                pi.x += vi.x; pi.y += vi.y; pi.z += vi.z; pi.w += vi.w;
                po.x += vo.x; po.y += vo.y; po.z += vo.z; po.w += vo.w;
                pa.x += va.x; pa.y += va.y; pa.z += va.z; pa.w += va.w;
            }
            float fv[4] = {pf.x, pf.y, pf.z, pf.w};
            float iv[4] = {pi.x, pi.y, pi.z, pi.w};
            float ov[4] = {po.x, po.y, po.z, po.w};
            float av[4] = {pa.x, pa.y, pa.z, pa.w};
            size_t base = (size_t)b * H_ + j;
            float4 cprev = *reinterpret_cast<const float4*>(&g_c[base]);
            float cp[4] = {cprev.x, cprev.y, cprev.z, cprev.w};
            float cnv[4], hnv[4];
            #pragma unroll
            for (int q = 0; q < 4; q++) {
                float ff = 1.f / (1.f + expf(-fv[q]));
                float ii = 1.f / (1.f + expf(-iv[q]));
                float oo = 1.f / (1.f + expf(-ov[q]));
                float cc = ii * tanhf(av[q]) + ff * cp[q];
                cnv[q] = cc;
                hnv[q] = oo * tanhf(cc);
            }
            float4 cn = {cnv[0], cnv[1], cnv[2], cnv[3]};
            float4 hn = {hnv[0], hnv[1], hnv[2], hnv[3]};
            *reinterpret_cast<float4*>(&g_c[base]) = cn;
            *reinterpret_cast<float4*>(&g_h[base]) = hn;
            *reinterpret_cast<float4*>(&g_Hbuf[(size_t)t * B_ * H_ + base]) = hn;
        }

        grid_barrier();
    }
}

// ---------------- launch ----------------
extern "C" void kernel_launch(void* const* d_in, const int* in_sizes, int n_in,
                              void* d_out, int out_size) {
    const float* x    = (const float*)d_in[0];
    const float* wfxw = (const float*)d_in[1];
    const float* wfxb = (const float*)d_in[2];
    const float* wixw = (const float*)d_in[3];
    const float* wixb = (const float*)d_in[4];
    const float* woxw = (const float*)d_in[5];
    const float* woxb = (const float*)d_in[6];
    const float* wcxw = (const float*)d_in[7];
    const float* wcxb = (const float*)d_in[8];
    const float* ufhw = (const float*)d_in[9];
    const float* uihw = (const float*)d_in[10];
    const float* uohw = (const float*)d_in[11];
    const float* uchw = (const float*)d_in[12];
    const float* fcow = (const float*)d_in[13];
    const float* fcob = (const float*)d_in[14];
    float* out = (float*)d_out;

    // recurrence is the 4th launch (ncu capture slot)
    build_W<<<(Fdim * N4 + 255) / 256, 256>>>(wfxw, wixw, woxw, wcxw);      // 1
    build_U_init<<<(H_ * N4 + 255) / 256, 256>>>(ufhw, uihw, uohw, uchw,
                                                 wfxb, wixb, woxb, wcxb);   // 2
    {   // input projections: G = x @ Wcat + bias                           // 3
        dim3 grid(N4 / 128, (T_ * B_) / 128);
        gemm_in<<<grid, 256>>>(x);
    }
    recurrence<<<NCTA, 256>>>();                                            // 4
    {   // output projection: out = Hbuf @ fco_w + fco_b                    // 5
        dim3 grid((FO + 127) / 128, (T_ * B_) / 128);
        gemm_out<<<grid, 256>>>(fcow, fcob, out);
    }
}

// round 16
// speedup vs baseline: 1.5107x; 1.5107x over previous
#include <cuda_runtime.h>
#include <math.h>

// Quaternion LSTM: T=128, B=64, F=512, H=1024.
// Round 16: R15 retry with the U-slice load loop bound FIXED (64 -> 16).
// Recurrence keeps its 128x128 U-slice resident in dynamic smem (loaded once,
// reused 128 steps); h slice staged once per step -> one sync + 128 straight
// FFMA-bound kk iterations. Math order bit-identical (rel_err 6.588118e-07).

#define T_ 128
#define B_ 64
#define Fdim 512
#define H_ 1024
#define N4 (4 * H_)          // 4096
#define FO (Fdim + 1)        // 513
#define SPLITK 8
#define KCHUNK (H_ / SPLITK) // 128
#define NCTA 256

// dynamic smem layout for recurrence (floats):
//   Us[128][132]  (U slice, padded)   = 16896 floats
//   As[128][68]   (h slice, padded)   =  8704 floats
#define US_PITCH 132
#define AS_PITCH 68
#define SMEM_FLOATS (128 * US_PITCH + 128 * AS_PITCH)
#define SMEM_BYTES (SMEM_FLOATS * 4)   // 102400 = 100 KB

// ---- scratch (static device globals: allocation-free) ----
__device__ float g_Wcat[(size_t)Fdim * N4];            //  8 MB
__device__ float g_bias4[N4];
__device__ float g_Ucat[(size_t)H_ * N4];              // 16 MB
__device__ float g_G[(size_t)T_ * B_ * N4];            // 128 MB (pre-gates)
__device__ float g_preK[(size_t)SPLITK * B_ * N4];     //  8 MB
__device__ float g_h[B_ * H_];
__device__ float g_c[B_ * H_];
__device__ float g_Hbuf[(size_t)T_ * B_ * H_];         // 32 MB
__device__ unsigned g_cnt;
__device__ volatile unsigned g_gen;

__device__ const float c_sgn[16] = {
    1.f, -1.f, -1.f, -1.f,
    1.f,  1.f, -1.f,  1.f,
    1.f,  1.f,  1.f, -1.f,
    1.f, -1.f,  1.f,  1.f
};

// ---------------- builds ----------------
__global__ void build_W(const float* __restrict__ wf, const float* __restrict__ wi,
                        const float* __restrict__ wo, const float* __restrict__ wc) {
    int idx = blockIdx.x * blockDim.x + threadIdx.x;
    if (idx >= Fdim * N4) return;
    int row  = idx / N4;
    int col  = idx % N4;
    int gate = col / H_;
    int cj   = col % H_;
    int rb = row / (Fdim / 4), a = row % (Fdim / 4);
    int cb = cj / (H_ / 4),    b = cj % (H_ / 4);
    const float* w = (gate == 0) ? wf : (gate == 1) ? wi : (gate == 2) ? wo : wc;
    g_Wcat[idx] = c_sgn[cb * 4 + rb] *
                  w[((size_t)(rb ^ cb) * (Fdim / 4) + a) * (H_ / 4) + b];
}

__global__ void build_U_init(const float* __restrict__ uf, const float* __restrict__ ui,
                             const float* __restrict__ uo, const float* __restrict__ uc,
                             const float* __restrict__ bf, const float* __restrict__ bi,
                             const float* __restrict__ bo, const float* __restrict__ bc) {
    int idx = blockIdx.x * blockDim.x + threadIdx.x;
    if (idx < B_ * H_) { g_h[idx] = 0.f; g_c[idx] = 0.f; }
    if (idx == 0) { g_cnt = 0; g_gen = 0; }
    if (idx < N4) {
        int gate = idx / H_, j = idx % H_;
        const float* b = (gate == 0) ? bf : (gate == 1) ? bi : (gate == 2) ? bo : bc;
        g_bias4[idx] = b[j];
    }
    if (idx >= H_ * N4) return;
    int row  = idx / N4;
    int col  = idx % N4;
    int gate = col / H_;
    int cj   = col % H_;
    int rb = row / (H_ / 4), a = row % (H_ / 4);
    int cb = cj / (H_ / 4),  b = cj % (H_ / 4);
    const float* w = (gate == 0) ? uf : (gate == 1) ? ui : (gate == 2) ? uo : uc;
    g_Ucat[idx] = c_sgn[cb * 4 + rb] *
                  w[((size_t)(rb ^ cb) * (H_ / 4) + a) * (H_ / 4) + b];
}

// ---------------- generic fp32 GEMM, double-buffered (R12-proven) ----------------
__device__ __forceinline__ void gemm_body(const float* __restrict__ A,
                                          const float* __restrict__ Bm,
                                          const float* __restrict__ bias,
                                          float* __restrict__ C,
                                          int M, int N, int K) {
    const int BM = 128, BN = 128, BK = 16;
    __shared__ __align__(16) float As[2][BK][BM];
    __shared__ __align__(16) float Bs[2][BK][BN];
    int tid = threadIdx.x;
    int tx = tid % 16, ty = tid / 16;
    int rowBase = blockIdx.y * BM;
    int colBase = blockIdx.x * BN;
    bool fullN = ((N & 3) == 0) && (colBase + BN <= N);
    float acc[8][8];
    #pragma unroll
    for (int i = 0; i < 8; i++)
        #pragma unroll
        for (int j = 0; j < 8; j++) acc[i][j] = 0.f;

    {   // preload chunk 0
        #pragma unroll
        for (int i = 0; i < 2; i++) {
            int lin = tid + i * 256;
            int r = lin >> 2, c4 = (lin & 3) * 4;
            float4 v = *reinterpret_cast<const float4*>(
                &A[(size_t)(rowBase + r) * K + c4]);
            As[0][c4 + 0][r] = v.x;
            As[0][c4 + 1][r] = v.y;
            As[0][c4 + 2][r] = v.z;
            As[0][c4 + 3][r] = v.w;
        }
        if (fullN) {
            #pragma unroll
            for (int i = 0; i < 2; i++) {
                int lin = tid + i * 256;
                int kk = lin >> 5, c4 = (lin & 31) * 4;
                float4 v = *reinterpret_cast<const float4*>(
                    &Bm[(size_t)kk * N + colBase + c4]);
                *reinterpret_cast<float4*>(&Bs[0][kk][c4]) = v;
            }
        } else {
            #pragma unroll
            for (int i = 0; i < 8; i++) {
                int lin = tid + i * 256;
                int kk = lin >> 7, n = lin & 127;
                int gn = colBase + n;
                Bs[0][kk][n] = (gn < N) ? Bm[(size_t)kk * N + gn] : 0.f;
            }
        }
    }
    __syncthreads();

    int buf = 0;
    for (int k0 = 0; k0 < K; k0 += BK) {
        bool more = (k0 + BK) < K;
        float4 pa[2];
        float4 pbv[2];
        float pbs[8];
        if (more) {
            int kn = k0 + BK;
            #pragma unroll
            for (int i = 0; i < 2; i++) {
                int lin = tid + i * 256;
                int r = lin >> 2, c4 = (lin & 3) * 4;
                pa[i] = *reinterpret_cast<const float4*>(
                    &A[(size_t)(rowBase + r) * K + kn + c4]);
            }
            if (fullN) {
                #pragma unroll
                for (int i = 0; i < 2; i++) {
                    int lin = tid + i * 256;
                    int kk = lin >> 5, c4 = (lin & 31) * 4;
                    pbv[i] = *reinterpret_cast<const float4*>(
                        &Bm[(size_t)(kn + kk) * N + colBase + c4]);
                }
            } else {
                #pragma unroll
                for (int i = 0; i < 8; i++) {
                    int lin = tid + i * 256;
                    int kk = lin >> 7, n = lin & 127;
                    int gn = colBase + n;
                    pbs[i] = (gn < N) ? Bm[(size_t)(kn + kk) * N + gn] : 0.f;
                }
            }
        }
        #pragma unroll
        for (int kk = 0; kk < BK; kk++) {
            float a[8], b[8];
            float4 a0 = *reinterpret_cast<const float4*>(&As[buf][kk][ty * 8]);
            float4 a1 = *reinterpret_cast<const float4*>(&As[buf][kk][ty * 8 + 4]);
            float4 b0 = *reinterpret_cast<const float4*>(&Bs[buf][kk][tx * 8]);
            float4 b1 = *reinterpret_cast<const float4*>(&Bs[buf][kk][tx * 8 + 4]);
            a[0]=a0.x; a[1]=a0.y; a[2]=a0.z; a[3]=a0.w;
            a[4]=a1.x; a[5]=a1.y; a[6]=a1.z; a[7]=a1.w;
            b[0]=b0.x; b[1]=b0.y; b[2]=b0.z; b[3]=b0.w;
            b[4]=b1.x; b[5]=b1.y; b[6]=b1.z; b[7]=b1.w;
            #pragma unroll
            for (int i = 0; i < 8; i++)
                #pragma unroll
                for (int j = 0; j < 8; j++)
                    acc[i][j] += a[i] * b[j];
        }
        if (more) {
            int nb = buf ^ 1;
            #pragma unroll
            for (int i = 0; i < 2; i++) {
                int lin = tid + i * 256;
                int r = lin >> 2, c4 = (lin & 3) * 4;
                As[nb][c4 + 0][r] = pa[i].x;
                As[nb][c4 + 1][r] = pa[i].y;
                As[nb][c4 + 2][r] = pa[i].z;
                As[nb][c4 + 3][r] = pa[i].w;
            }
            if (fullN) {
                #pragma unroll
                for (int i = 0; i < 2; i++) {
                    int lin = tid + i * 256;
                    int kk = lin >> 5, c4 = (lin & 31) * 4;
                    *reinterpret_cast<float4*>(&Bs[nb][kk][c4]) = pbv[i];
                }
            } else {
                #pragma unroll
                for (int i = 0; i < 8; i++) {
                    int lin = tid + i * 256;
                    int kk = lin >> 7, n = lin & 127;
                    Bs[nb][kk][n] = pbs[i];
                }
            }
        }
        __syncthreads();
        buf ^= 1;
    }
    #pragma unroll
    for (int i = 0; i < 8; i++) {
        int gm = rowBase + ty * 8 + i;
        if (gm >= M) continue;
        #pragma unroll
        for (int j = 0; j < 8; j++) {
            int gn = colBase + tx * 8 + j;
            if (gn >= N) continue;
            float v = acc[i][j];
            if (bias) v += bias[gn];
            C[(size_t)gm * N + gn] = v;
        }
    }
}

__global__ __launch_bounds__(256) void gemm_in(const float* __restrict__ x) {
    gemm_body(x, g_Wcat, g_bias4, g_G, T_ * B_, N4, Fdim);
}

__global__ __launch_bounds__(256) void gemm_out(const float* __restrict__ fw,
                                                const float* __restrict__ fb,
                                                float* __restrict__ out) {
    gemm_body(g_Hbuf, fw, fb, out, T_ * B_, FO, H_);
}

// ---------------- grid barrier (R7-proven) ----------------
__device__ __forceinline__ void grid_barrier() {
    __syncthreads();
    __threadfence();
    if (threadIdx.x == 0) {
        unsigned gen = g_gen;
        unsigned prev = atomicAdd(&g_cnt, 1u);
        if (prev == NCTA - 1) {
            g_cnt = 0;
            __threadfence();
            g_gen = gen + 1;
        } else {
            while (g_gen == gen) { }
        }
    }
    __syncthreads();
    __threadfence();
}

// ---------------- persistent recurrence: U slice resident in smem ------------
__global__ __launch_bounds__(256, 2) void recurrence() {
    extern __shared__ __align__(16) float smem[];
    float* Us = smem;                      // [128][US_PITCH]
    float* As = smem + 128 * US_PITCH;     // [128][AS_PITCH]
    int tid = threadIdx.x;
    int tx = tid & 15, ty = tid >> 4;
    int nTile = blockIdx.x & 31;
    int s = blockIdx.x >> 5;
    int colBase = nTile * 128;
    int kbase = s * KCHUNK;
    int gtid = blockIdx.x * 256 + tid;
    float* preOut = g_preK + (size_t)s * B_ * N4;

    // ---- one-time U slice load: 128x128 floats = 4096 float4s / 256 thr = 16
    #pragma unroll
    for (int i = 0; i < 16; i++) {
        int lin = tid + i * 256;           // 0..4095 float4-slots
        int kk = lin >> 5, c4 = (lin & 31) * 4;
        float4 v = *reinterpret_cast<const float4*>(
            &g_Ucat[(size_t)(kbase + kk) * N4 + colBase + c4]);
        *reinterpret_cast<float4*>(&Us[kk * US_PITCH + c4]) = v;
    }
    __syncthreads();

    for (int t = 0; t < T_; t++) {
        // ======== phase 1: stage full h slice, then 128 straight kk iters
        #pragma unroll
        for (int i = 0; i < 8; i++) {
            int lin = tid + i * 256;       // 0..2047 float4-slots
            int r = lin >> 5, kq = (lin & 31) * 4;
            float4 v = *reinterpret_cast<const float4*>(
                &g_h[(size_t)r * H_ + kbase + kq]);
            As[(kq + 0) * AS_PITCH + r] = v.x;
            As[(kq + 1) * AS_PITCH + r] = v.y;
            As[(kq + 2) * AS_PITCH + r] = v.z;
            As[(kq + 3) * AS_PITCH + r] = v.w;
        }
        __syncthreads();

        float acc[4][8];
        #pragma unroll
        for (int i = 0; i < 4; i++)
            #pragma unroll
            for (int j = 0; j < 8; j++) acc[i][j] = 0.f;

        #pragma unroll 8
        for (int kk = 0; kk < 128; kk++) {
            float4 av = *reinterpret_cast<const float4*>(&As[kk * AS_PITCH + ty * 4]);
            float4 b0 = *reinterpret_cast<const float4*>(&Us[kk * US_PITCH + tx * 8]);
            float4 b1 = *reinterpret_cast<const float4*>(&Us[kk * US_PITCH + tx * 8 + 4]);
            float a[4] = {av.x, av.y, av.z, av.w};
            float b[8] = {b0.x, b0.y, b0.z, b0.w, b1.x, b1.y, b1.z, b1.w};
            #pragma unroll
            for (int i = 0; i < 4; i++)
                #pragma unroll
                for (int j = 0; j < 8; j++)
                    acc[i][j] += a[i] * b[j];
        }
        __syncthreads();
        #pragma unroll
        for (int i = 0; i < 4; i++) {
            int r = ty * 4 + i;
            float4 v0 = {acc[i][0], acc[i][1], acc[i][2], acc[i][3]};
            float4 v1 = {acc[i][4], acc[i][5], acc[i][6], acc[i][7]};
            *reinterpret_cast<float4*>(&preOut[(size_t)r * N4 + colBase + tx * 8])     = v0;
            *reinterpret_cast<float4*>(&preOut[(size_t)r * N4 + colBase + tx * 8 + 4]) = v1;
        }

        grid_barrier();

        // ======== phase 2: gates + state update (concentrated: CTAs 0-63)
        if (gtid < B_ * H_ / 4) {
            int b = gtid / (H_ / 4);
            int j = (gtid % (H_ / 4)) * 4;
            const float* Gt = g_G + (size_t)((size_t)t * B_ + b) * N4;
            float4 pf = *reinterpret_cast<const float4*>(&Gt[0 * H_ + j]);
            float4 pi = *reinterpret_cast<const float4*>(&Gt[1 * H_ + j]);
            float4 po = *reinterpret_cast<const float4*>(&Gt[2 * H_ + j]);
            float4 pa = *reinterpret_cast<const float4*>(&Gt[3 * H_ + j]);
            #pragma unroll
            for (int sp = 0; sp < SPLITK; sp++) {
                const float* pk = g_preK + (size_t)sp * B_ * N4 + (size_t)b * N4;
                float4 vf = *reinterpret_cast<const float4*>(&pk[0 * H_ + j]);
                float4 vi = *reinterpret_cast<const float4*>(&pk[1 * H_ + j]);
                float4 vo = *reinterpret_cast<const float4*>(&pk[2 * H_ + j]);
                float4 va = *reinterpret_cast<const float4*>(&pk[3 * H_ + j]);
                pf.x += vf.x; pf.y += vf.y; pf.z += vf.z; pf.w += vf.w;
                pi.x += vi.x; pi.y += vi.y; pi.z += vi.z; pi.w += vi.w;
                po.x += vo.x; po.y += vo.y; po.z += vo.z; po.w += vo.w;
                pa.x += va.x; pa.y += va.y; pa.z += va.z; pa.w += va.w;
            }
            float fv[4] = {pf.x, pf.y, pf.z, pf.w};
            float iv[4] = {pi.x, pi.y, pi.z, pi.w};
            float ov[4] = {po.x, po.y, po.z, po.w};
            float av[4] = {pa.x, pa.y, pa.z, pa.w};
            size_t base = (size_t)b * H_ + j;
            float4 cprev = *reinterpret_cast<const float4*>(&g_c[base]);
            float cp[4] = {cprev.x, cprev.y, cprev.z, cprev.w};
            float cnv[4], hnv[4];
            #pragma unroll
            for (int q = 0; q < 4; q++) {
                float ff = 1.f / (1.f + expf(-fv[q]));
                float ii = 1.f / (1.f + expf(-iv[q]));
                float oo = 1.f / (1.f + expf(-ov[q]));
                float cc = ii * tanhf(av[q]) + ff * cp[q];
                cnv[q] = cc;
                hnv[q] = oo * tanhf(cc);
            }
            float4 cn = {cnv[0], cnv[1], cnv[2], cnv[3]};
            float4 hn = {hnv[0], hnv[1], hnv[2], hnv[3]};
            *reinterpret_cast<float4*>(&g_c[base]) = cn;
            *reinterpret_cast<float4*>(&g_h[base]) = hn;
            *reinterpret_cast<float4*>(&g_Hbuf[(size_t)t * B_ * H_ + base]) = hn;
        }

        grid_barrier();
    }
}

// ---------------- launch ----------------
extern "C" void kernel_launch(void* const* d_in, const int* in_sizes, int n_in,
                              void* d_out, int out_size) {
    const float* x    = (const float*)d_in[0];
    const float* wfxw = (const float*)d_in[1];
    const float* wfxb = (const float*)d_in[2];
    const float* wixw = (const float*)d_in[3];
    const float* wixb = (const float*)d_in[4];
    const float* woxw = (const float*)d_in[5];
    const float* woxb = (const float*)d_in[6];
    const float* wcxw = (const float*)d_in[7];
    const float* wcxb = (const float*)d_in[8];
    const float* ufhw = (const float*)d_in[9];
    const float* uihw = (const float*)d_in[10];
    const float* uohw = (const float*)d_in[11];
    const float* uchw = (const float*)d_in[12];
    const float* fcow = (const float*)d_in[13];
    const float* fcob = (const float*)d_in[14];
    float* out = (float*)d_out;

    static int smemSet = 0;
    if (!smemSet) {
        cudaFuncSetAttribute(recurrence,
                             cudaFuncAttributeMaxDynamicSharedMemorySize,
                             SMEM_BYTES);
        smemSet = 1;
    }

    // recurrence is the 4th launch (ncu capture slot)
    build_W<<<(Fdim * N4 + 255) / 256, 256>>>(wfxw, wixw, woxw, wcxw);      // 1
    build_U_init<<<(H_ * N4 + 255) / 256, 256>>>(ufhw, uihw, uohw, uchw,
                                                 wfxb, wixb, woxb, wcxb);   // 2
    {   // input projections: G = x @ Wcat + bias                           // 3
        dim3 grid(N4 / 128, (T_ * B_) / 128);
        gemm_in<<<grid, 256>>>(x);
    }
    recurrence<<<NCTA, 256, SMEM_BYTES>>>();                                // 4
    {   // output projection: out = Hbuf @ fco_w + fco_b                    // 5
        dim3 grid((FO + 127) / 128, (T_ * B_) / 128);
        gemm_out<<<grid, 256>>>(fcow, fcob, out);
    }
}

// round 17
// speedup vs baseline: 1.6443x; 1.0885x over previous
#include <cuda_runtime.h>
#include <math.h>

// Quaternion LSTM: T=128, B=64, F=512, H=1024.
// Round 17: R16 with the h-stage BANK CONFLICT fixed:
//   As stored [r][k] (pitch 132) -> staging stores conflict-free (lanes write
//   consecutive float4s). kk-loop reads A via 4 scalar broadcast LDS.
//   U slice stays resident in smem (loaded once, reused 128 steps).
// Math order bit-identical (rel_err must stay 6.588118e-07).

#define T_ 128
#define B_ 64
#define Fdim 512
#define H_ 1024
#define N4 (4 * H_)          // 4096
#define FO (Fdim + 1)        // 513
#define SPLITK 8
#define KCHUNK (H_ / SPLITK) // 128
#define NCTA 256

// dynamic smem (floats): Us[128][132] + As[64][132]
#define US_PITCH 132
#define AS_PITCH 132
#define SMEM_FLOATS (128 * US_PITCH + 64 * AS_PITCH)
#define SMEM_BYTES (SMEM_FLOATS * 4)   // 101376 B ~ 99 KB

// ---- scratch (static device globals: allocation-free) ----
__device__ float g_Wcat[(size_t)Fdim * N4];            //  8 MB
__device__ float g_bias4[N4];
__device__ float g_Ucat[(size_t)H_ * N4];              // 16 MB
__device__ float g_G[(size_t)T_ * B_ * N4];            // 128 MB (pre-gates)
__device__ float g_preK[(size_t)SPLITK * B_ * N4];     //  8 MB
__device__ float g_h[B_ * H_];
__device__ float g_c[B_ * H_];
__device__ float g_Hbuf[(size_t)T_ * B_ * H_];         // 32 MB
__device__ unsigned g_cnt;
__device__ volatile unsigned g_gen;

__device__ const float c_sgn[16] = {
    1.f, -1.f, -1.f, -1.f,
    1.f,  1.f, -1.f,  1.f,
    1.f,  1.f,  1.f, -1.f,
    1.f, -1.f,  1.f,  1.f
};

// ---------------- builds ----------------
__global__ void build_W(const float* __restrict__ wf, const float* __restrict__ wi,
                        const float* __restrict__ wo, const float* __restrict__ wc) {
    int idx = blockIdx.x * blockDim.x + threadIdx.x;
    if (idx >= Fdim * N4) return;
    int row  = idx / N4;
    int col  = idx % N4;
    int gate = col / H_;
    int cj   = col % H_;
    int rb = row / (Fdim / 4), a = row % (Fdim / 4);
    int cb = cj / (H_ / 4),    b = cj % (H_ / 4);
    const float* w = (gate == 0) ? wf : (gate == 1) ? wi : (gate == 2) ? wo : wc;
    g_Wcat[idx] = c_sgn[cb * 4 + rb] *
                  w[((size_t)(rb ^ cb) * (Fdim / 4) + a) * (H_ / 4) + b];
}

__global__ void build_U_init(const float* __restrict__ uf, const float* __restrict__ ui,
                             const float* __restrict__ uo, const float* __restrict__ uc,
                             const float* __restrict__ bf, const float* __restrict__ bi,
                             const float* __restrict__ bo, const float* __restrict__ bc) {
    int idx = blockIdx.x * blockDim.x + threadIdx.x;
    if (idx < B_ * H_) { g_h[idx] = 0.f; g_c[idx] = 0.f; }
    if (idx == 0) { g_cnt = 0; g_gen = 0; }
    if (idx < N4) {
        int gate = idx / H_, j = idx % H_;
        const float* b = (gate == 0) ? bf : (gate == 1) ? bi : (gate == 2) ? bo : bc;
        g_bias4[idx] = b[j];
    }
    if (idx >= H_ * N4) return;
    int row  = idx / N4;
    int col  = idx % N4;
    int gate = col / H_;
    int cj   = col % H_;
    int rb = row / (H_ / 4), a = row % (H_ / 4);
    int cb = cj / (H_ / 4),  b = cj % (H_ / 4);
    const float* w = (gate == 0) ? uf : (gate == 1) ? ui : (gate == 2) ? uo : uc;
    g_Ucat[idx] = c_sgn[cb * 4 + rb] *
                  w[((size_t)(rb ^ cb) * (H_ / 4) + a) * (H_ / 4) + b];
}

// ---------------- generic fp32 GEMM, double-buffered (R12-proven) ----------------
__device__ __forceinline__ void gemm_body(const float* __restrict__ A,
                                          const float* __restrict__ Bm,
                                          const float* __restrict__ bias,
                                          float* __restrict__ C,
                                          int M, int N, int K) {
    const int BM = 128, BN = 128, BK = 16;
    __shared__ __align__(16) float As[2][BK][BM];
    __shared__ __align__(16) float Bs[2][BK][BN];
    int tid = threadIdx.x;
    int tx = tid % 16, ty = tid / 16;
    int rowBase = blockIdx.y * BM;
    int colBase = blockIdx.x * BN;
    bool fullN = ((N & 3) == 0) && (colBase + BN <= N);
    float acc[8][8];
    #pragma unroll
    for (int i = 0; i < 8; i++)
        #pragma unroll
        for (int j = 0; j < 8; j++) acc[i][j] = 0.f;

    {   // preload chunk 0
        #pragma unroll
        for (int i = 0; i < 2; i++) {
            int lin = tid + i * 256;
            int r = lin >> 2, c4 = (lin & 3) * 4;
            float4 v = *reinterpret_cast<const float4*>(
                &A[(size_t)(rowBase + r) * K + c4]);
            As[0][c4 + 0][r] = v.x;
            As[0][c4 + 1][r] = v.y;
            As[0][c4 + 2][r] = v.z;
            As[0][c4 + 3][r] = v.w;
        }
        if (fullN) {
            #pragma unroll
            for (int i = 0; i < 2; i++) {
                int lin = tid + i * 256;
                int kk = lin >> 5, c4 = (lin & 31) * 4;
                float4 v = *reinterpret_cast<const float4*>(
                    &Bm[(size_t)kk * N + colBase + c4]);
                *reinterpret_cast<float4*>(&Bs[0][kk][c4]) = v;
            }
        } else {
            #pragma unroll
            for (int i = 0; i < 8; i++) {
                int lin = tid + i * 256;
                int kk = lin >> 7, n = lin & 127;
                int gn = colBase + n;
                Bs[0][kk][n] = (gn < N) ? Bm[(size_t)kk * N + gn] : 0.f;
            }
        }
    }
    __syncthreads();

    int buf = 0;
    for (int k0 = 0; k0 < K; k0 += BK) {
        bool more = (k0 + BK) < K;
        float4 pa[2];
        float4 pbv[2];
        float pbs[8];
        if (more) {
            int kn = k0 + BK;
            #pragma unroll
            for (int i = 0; i < 2; i++) {
                int lin = tid + i * 256;
                int r = lin >> 2, c4 = (lin & 3) * 4;
                pa[i] = *reinterpret_cast<const float4*>(
                    &A[(size_t)(rowBase + r) * K + kn + c4]);
            }
            if (fullN) {
                #pragma unroll
                for (int i = 0; i < 2; i++) {
                    int lin = tid + i * 256;
                    int kk = lin >> 5, c4 = (lin & 31) * 4;
                    pbv[i] = *reinterpret_cast<const float4*>(
                        &Bm[(size_t)(kn + kk) * N + colBase + c4]);
                }
            } else {
                #pragma unroll
                for (int i = 0; i < 8; i++) {
                    int lin = tid + i * 256;
                    int kk = lin >> 7, n = lin & 127;
                    int gn = colBase + n;
                    pbs[i] = (gn < N) ? Bm[(size_t)(kn + kk) * N + gn] : 0.f;
                }
            }
        }
        #pragma unroll
        for (int kk = 0; kk < BK; kk++) {
            float a[8], b[8];
            float4 a0 = *reinterpret_cast<const float4*>(&As[buf][kk][ty * 8]);
            float4 a1 = *reinterpret_cast<const float4*>(&As[buf][kk][ty * 8 + 4]);
            float4 b0 = *reinterpret_cast<const float4*>(&Bs[buf][kk][tx * 8]);
            float4 b1 = *reinterpret_cast<const float4*>(&Bs[buf][kk][tx * 8 + 4]);
            a[0]=a0.x; a[1]=a0.y; a[2]=a0.z; a[3]=a0.w;
            a[4]=a1.x; a[5]=a1.y; a[6]=a1.z; a[7]=a1.w;
            b[0]=b0.x; b[1]=b0.y; b[2]=b0.z; b[3]=b0.w;
            b[4]=b1.x; b[5]=b1.y; b[6]=b1.z; b[7]=b1.w;
            #pragma unroll
            for (int i = 0; i < 8; i++)
                #pragma unroll
                for (int j = 0; j < 8; j++)
                    acc[i][j] += a[i] * b[j];
        }
        if (more) {
            int nb = buf ^ 1;
            #pragma unroll
            for (int i = 0; i < 2; i++) {
                int lin = tid + i * 256;
                int r = lin >> 2, c4 = (lin & 3) * 4;
                As[nb][c4 + 0][r] = pa[i].x;
                As[nb][c4 + 1][r] = pa[i].y;
                As[nb][c4 + 2][r] = pa[i].z;
                As[nb][c4 + 3][r] = pa[i].w;
            }
            if (fullN) {
                #pragma unroll
                for (int i = 0; i < 2; i++) {
                    int lin = tid + i * 256;
                    int kk = lin >> 5, c4 = (lin & 31) * 4;
                    *reinterpret_cast<float4*>(&Bs[nb][kk][c4]) = pbv[i];
                }
            } else {
                #pragma unroll
                for (int i = 0; i < 8; i++) {
                    int lin = tid + i * 256;
                    int kk = lin >> 7, n = lin & 127;
                    Bs[nb][kk][n] = pbs[i];
                }
            }
        }
        __syncthreads();
        buf ^= 1;
    }
    #pragma unroll
    for (int i = 0; i < 8; i++) {
        int gm = rowBase + ty * 8 + i;
        if (gm >= M) continue;
        #pragma unroll
        for (int j = 0; j < 8; j++) {
            int gn = colBase + tx * 8 + j;
            if (gn >= N) continue;
            float v = acc[i][j];
            if (bias) v += bias[gn];
            C[(size_t)gm * N + gn] = v;
        }
    }
}

__global__ __launch_bounds__(256) void gemm_in(const float* __restrict__ x) {
    gemm_body(x, g_Wcat, g_bias4, g_G, T_ * B_, N4, Fdim);
}

__global__ __launch_bounds__(256) void gemm_out(const float* __restrict__ fw,
                                                const float* __restrict__ fb,
                                                float* __restrict__ out) {
    gemm_body(g_Hbuf, fw, fb, out, T_ * B_, FO, H_);
}

// ---------------- grid barrier (R7-proven) ----------------
__device__ __forceinline__ void grid_barrier() {
    __syncthreads();
    __threadfence();
    if (threadIdx.x == 0) {
        unsigned gen = g_gen;
        unsigned prev = atomicAdd(&g_cnt, 1u);
        if (prev == NCTA - 1) {
            g_cnt = 0;
            __threadfence();
            g_gen = gen + 1;
        } else {
            while (g_gen == gen) { }
        }
    }
    __syncthreads();
    __threadfence();
}

// ---------------- persistent recurrence: U resident, conflict-free h-stage ----
__global__ __launch_bounds__(256, 2) void recurrence() {
    extern __shared__ __align__(16) float smem[];
    float* Us = smem;                      // [128][US_PITCH]  (k-major)
    float* As = smem + 128 * US_PITCH;     // [64][AS_PITCH]   (r-major!)
    int tid = threadIdx.x;
    int tx = tid & 15, ty = tid >> 4;
    int nTile = blockIdx.x & 31;
    int s = blockIdx.x >> 5;
    int colBase = nTile * 128;
    int kbase = s * KCHUNK;
    int gtid = blockIdx.x * 256 + tid;
    float* preOut = g_preK + (size_t)s * B_ * N4;

    // ---- one-time U slice load: 128x128 floats = 4096 float4s
    #pragma unroll
    for (int i = 0; i < 16; i++) {
        int lin = tid + i * 256;
        int kk = lin >> 5, c4 = (lin & 31) * 4;
        float4 v = *reinterpret_cast<const float4*>(
            &g_Ucat[(size_t)(kbase + kk) * N4 + colBase + c4]);
        *reinterpret_cast<float4*>(&Us[kk * US_PITCH + c4]) = v;
    }
    __syncthreads();

    for (int t = 0; t < T_; t++) {
        // ======== phase 1: stage h slice [r][k] (conflict-free stores)
        #pragma unroll
        for (int i = 0; i < 8; i++) {
            int lin = tid + i * 256;       // 2048 float4s = 64 r x 32 kq
            int r = lin >> 5, kq = (lin & 31) * 4;
            float4 v = *reinterpret_cast<const float4*>(
                &g_h[(size_t)r * H_ + kbase + kq]);
            *reinterpret_cast<float4*>(&As[r * AS_PITCH + kq]) = v;
        }
        __syncthreads();

        float acc[4][8];
        #pragma unroll
        for (int i = 0; i < 4; i++)
            #pragma unroll
            for (int j = 0; j < 8; j++) acc[i][j] = 0.f;

        #pragma unroll 8
        for (int kk = 0; kk < 128; kk++) {
            float a[4];
            #pragma unroll
            for (int i = 0; i < 4; i++)
                a[i] = As[(ty * 4 + i) * AS_PITCH + kk];   // broadcast LDS
            float4 b0 = *reinterpret_cast<const float4*>(&Us[kk * US_PITCH + tx * 8]);
            float4 b1 = *reinterpret_cast<const float4*>(&Us[kk * US_PITCH + tx * 8 + 4]);
            float b[8] = {b0.x, b0.y, b0.z, b0.w, b1.x, b1.y, b1.z, b1.w};
            #pragma unroll
            for (int i = 0; i < 4; i++)
                #pragma unroll
                for (int j = 0; j < 8; j++)
                    acc[i][j] += a[i] * b[j];
        }
        __syncthreads();
        #pragma unroll
        for (int i = 0; i < 4; i++) {
            int r = ty * 4 + i;
            float4 v0 = {acc[i][0], acc[i][1], acc[i][2], acc[i][3]};
            float4 v1 = {acc[i][4], acc[i][5], acc[i][6], acc[i][7]};
            *reinterpret_cast<float4*>(&preOut[(size_t)r * N4 + colBase + tx * 8])     = v0;
            *reinterpret_cast<float4*>(&preOut[(size_t)r * N4 + colBase + tx * 8 + 4]) = v1;
        }

        grid_barrier();

        // ======== phase 2: gates + state update (concentrated: CTAs 0-63)
        if (gtid < B_ * H_ / 4) {
            int b = gtid / (H_ / 4);
            int j = (gtid % (H_ / 4)) * 4;
            const float* Gt = g_G + (size_t)((size_t)t * B_ + b) * N4;
            float4 pf = *reinterpret_cast<const float4*>(&Gt[0 * H_ + j]);
            float4 pi = *reinterpret_cast<const float4*>(&Gt[1 * H_ + j]);
            float4 po = *reinterpret_cast<const float4*>(&Gt[2 * H_ + j]);
            float4 pa = *reinterpret_cast<const float4*>(&Gt[3 * H_ + j]);
            #pragma unroll
            for (int sp = 0; sp < SPLITK; sp++) {
                const float* pk = g_preK + (size_t)sp * B_ * N4 + (size_t)b * N4;
                float4 vf = *reinterpret_cast<const float4*>(&pk[0 * H_ + j]);
                float4 vi = *reinterpret_cast<const float4*>(&pk[1 * H_ + j]);
                float4 vo = *reinterpret_cast<const float4*>(&pk[2 * H_ + j]);
                float4 va = *reinterpret_cast<const float4*>(&pk[3 * H_ + j]);
                pf.x += vf.x; pf.y += vf.y; pf.z += vf.z; pf.w += vf.w;
                pi.x += vi.x; pi.y += vi.y; pi.z += vi.z; pi.w += vi.w;
                po.x += vo.x; po.y += vo.y; po.z += vo.z; po.w += vo.w;
                pa.x += va.x; pa.y += va.y; pa.z += va.z; pa.w += va.w;
            }
            float fv[4] = {pf.x, pf.y, pf.z, pf.w};
            float iv[4] = {pi.x, pi.y, pi.z, pi.w};
            float ov[4] = {po.x, po.y, po.z, po.w};
            float av[4] = {pa.x, pa.y, pa.z, pa.w};
            size_t base = (size_t)b * H_ + j;
            float4 cprev = *reinterpret_cast<const float4*>(&g_c[base]);
            float cp[4] = {cprev.x, cprev.y, cprev.z, cprev.w};
            float cnv[4], hnv[4];
            #pragma unroll
            for (int q = 0; q < 4; q++) {
                float ff = 1.f / (1.f + expf(-fv[q]));
                float ii = 1.f / (1.f + expf(-iv[q]));
                float oo = 1.f / (1.f + expf(-ov[q]));
                float cc = ii * tanhf(av[q]) + ff * cp[q];
                cnv[q] = cc;
                hnv[q] = oo * tanhf(cc);
            }
            float4 cn = {cnv[0], cnv[1], cnv[2], cnv[3]};
            float4 hn = {hnv[0], hnv[1], hnv[2], hnv[3]};
            *reinterpret_cast<float4*>(&g_c[base]) = cn;
            *reinterpret_cast<float4*>(&g_h[base]) = hn;
            *reinterpret_cast<float4*>(&g_Hbuf[(size_t)t * B_ * H_ + base]) = hn;
        }

        grid_barrier();
    }
}

// ---------------- launch ----------------
extern "C" void kernel_launch(void* const* d_in, const int* in_sizes, int n_in,
                              void* d_out, int out_size) {
    const float* x    = (const float*)d_in[0];
    const float* wfxw = (const float*)d_in[1];
    const float* wfxb = (const float*)d_in[2];
    const float* wixw = (const float*)d_in[3];
    const float* wixb = (const float*)d_in[4];
    const float* woxw = (const float*)d_in[5];
    const float* woxb = (const float*)d_in[6];
    const float* wcxw = (const float*)d_in[7];
    const float* wcxb = (const float*)d_in[8];
    const float* ufhw = (const float*)d_in[9];
    const float* uihw = (const float*)d_in[10];
    const float* uohw = (const float*)d_in[11];
    const float* uchw = (const float*)d_in[12];
    const float* fcow = (const float*)d_in[13];
    const float* fcob = (const float*)d_in[14];
    float* out = (float*)d_out;

    static int smemSet = 0;
    if (!smemSet) {
        cudaFuncSetAttribute(recurrence,
                             cudaFuncAttributeMaxDynamicSharedMemorySize,
                             SMEM_BYTES);
        smemSet = 1;
    }

    // recurrence is the 4th launch (ncu capture slot)
    build_W<<<(Fdim * N4 + 255) / 256, 256>>>(wfxw, wixw, woxw, wcxw);      // 1
    build_U_init<<<(H_ * N4 + 255) / 256, 256>>>(ufhw, uihw, uohw, uchw,
                                                 wfxb, wixb, woxb, wcxb);   // 2
    {   // input projections: G = x @ Wcat + bias                           // 3
        dim3 grid(N4 / 128, (T_ * B_) / 128);
        gemm_in<<<grid, 256>>>(x);
    }
    recurrence<<<NCTA, 256, SMEM_BYTES>>>();                                // 4
    {   // output projection: out = Hbuf @ fco_w + fco_b                    // 5
        dim3 grid((FO + 127) / 128, (T_ * B_) / 128);
        gemm_out<<<grid, 256>>>(fcow, fcob, out);
    }
}